// round 4
// baseline (speedup 1.0000x reference)
#include <cuda_runtime.h>
#include <cuda_bf16.h>
#include <cstdint>

#define B_   16
#define TQ_  128
#define TK_  256
#define DIN_ 64
#define H_   256
#define DV_  256
#define IT_  4
#define NEGV (-1000000.0f)

// Scratch for projected q/k (static device arrays: allocation-free).
__device__ float g_q[B_ * TQ_ * H_];   // [B, Tq, H]
__device__ float g_k[B_ * TK_ * H_];   // [B, Tk, H]

__device__ __forceinline__ float fast_tanh(float x) {
    float y;
    asm("tanh.approx.f32 %0, %1;" : "=f"(y) : "f"(x));
    return y;
}

// ---------------------------------------------------------------------------
// Kernel 1: projections  g_q = queries @ wq,  g_k = keys @ wk
// ---------------------------------------------------------------------------
__global__ __launch_bounds__(256) void proj_kernel(
    const float* __restrict__ queries, const float* __restrict__ keys,
    const float* __restrict__ wq, const float* __restrict__ wk)
{
    constexpr int RPB = 32;
    int blk = blockIdx.x;
    const float* X; const float* W; float* Y; int row0;
    constexpr int QBLKS = (B_ * TQ_) / RPB;   // 64
    if (blk < QBLKS) { X = queries; W = wq; Y = g_q; row0 = blk * RPB; }
    else             { X = keys;    W = wk; Y = g_k; row0 = (blk - QBLKS) * RPB; }

    const int tid = threadIdx.x;

    float w[DIN_];
    #pragma unroll
    for (int d = 0; d < DIN_; d++) w[d] = W[d * H_ + tid];   // coalesced

    __shared__ __align__(16) float s_x[RPB][DIN_];           // 8 KB
    const float* xb = X + (size_t)row0 * DIN_;
    #pragma unroll
    for (int k = 0; k < (RPB * DIN_) / 256; k++)
        ((float*)s_x)[tid + k * 256] = xb[tid + k * 256];
    __syncthreads();

    #pragma unroll 4
    for (int r = 0; r < RPB; r++) {
        const float4* xr = (const float4*)s_x[r];
        float acc = 0.f;
        #pragma unroll
        for (int d4 = 0; d4 < DIN_ / 4; d4++) {
            float4 xv = xr[d4];
            acc += xv.x * w[d4 * 4 + 0];
            acc += xv.y * w[d4 * 4 + 1];
            acc += xv.z * w[d4 * 4 + 2];
            acc += xv.w * w[d4 * 4 + 3];
        }
        Y[(size_t)(row0 + r) * H_ + tid] = acc;
    }
}

// ---------------------------------------------------------------------------
// Kernel 2: fused scores + masked softmax + attn@V.
// One CTA = (batch b, tile of IT_=4 query rows). 256 threads, 512 CTAs.
//   Phase 1: thread t owns key row j=t; accumulates IT_ scores while
//            streaming k[b,t,:] as float4 (L2-resident, prefetched) and
//            reading q/wv via SMEM broadcast.
//   Softmax: warps 0..IT_-1 each own one row, in-SMEM.
//   Phase 2: thread t owns output column v=t; coalesced values loads.
// ---------------------------------------------------------------------------
__global__ __launch_bounds__(256, 4) void attn_kernel(
    const float* __restrict__ values, const int* __restrict__ valid_lens,
    const float* __restrict__ wv, float* __restrict__ out)
{
    const int b  = blockIdx.x >> 5;          // 32 q-tiles per batch
    const int i0 = (blockIdx.x & 31) * IT_;
    const int tid = threadIdx.x;

    __shared__ __align__(16) float s_q[IT_][H_];    // 4 KB
    __shared__ __align__(16) float s_wv[H_];        // 1 KB
    __shared__ __align__(16) float s_sc[IT_][TK_];  // 4 KB (scores -> attn)

    s_wv[tid] = wv[tid];
    #pragma unroll
    for (int i = 0; i < IT_; i++)
        s_q[i][tid] = g_q[((size_t)b * TQ_ + i0 + i) * H_ + tid];
    const int vl = valid_lens[b];
    __syncthreads();

    // ---- Phase 1: additive-attention scores (MUFU.TANH-bound) ----
    const float4* krow = (const float4*)(g_k + ((size_t)b * TK_ + tid) * H_);
    float acc[IT_];
    #pragma unroll
    for (int i = 0; i < IT_; i++) acc[i] = 0.f;

    float4 kv = krow[0];
    #pragma unroll 4
    for (int h4 = 0; h4 < H_ / 4; h4++) {
        float4 kn;
        if (h4 + 1 < H_ / 4) kn = krow[h4 + 1];      // prefetch next
        float4 wvv = ((const float4*)s_wv)[h4];
        #pragma unroll
        for (int i = 0; i < IT_; i++) {
            float4 qv = ((const float4*)s_q[i])[h4];
            acc[i] += wvv.x * fast_tanh(qv.x + kv.x);
            acc[i] += wvv.y * fast_tanh(qv.y + kv.y);
            acc[i] += wvv.z * fast_tanh(qv.z + kv.z);
            acc[i] += wvv.w * fast_tanh(qv.w + kv.w);
        }
        kv = kn;
    }
    #pragma unroll
    for (int i = 0; i < IT_; i++)
        s_sc[i][tid] = (tid < vl) ? acc[i] : NEGV;
    __syncthreads();

    // ---- Masked softmax: warp w (w < IT_) handles row i=w ----
    if (tid < IT_ * 32) {
        const int i = tid >> 5, lane = tid & 31;
        float v[TK_ / 32];
        float m = -3.402823466e38f;
        #pragma unroll
        for (int k = 0; k < TK_ / 32; k++) {
            v[k] = s_sc[i][lane + k * 32];
            m = fmaxf(m, v[k]);
        }
        #pragma unroll
        for (int off = 16; off; off >>= 1)
            m = fmaxf(m, __shfl_xor_sync(0xffffffffu, m, off));
        float sum = 0.f;
        #pragma unroll
        for (int k = 0; k < TK_ / 32; k++) {
            v[k] = __expf(v[k] - m);
            sum += v[k];
        }
        #pragma unroll
        for (int off = 16; off; off >>= 1)
            sum += __shfl_xor_sync(0xffffffffu, sum, off);
        const float inv = 1.0f / sum;
        #pragma unroll
        for (int k = 0; k < TK_ / 32; k++)
            s_sc[i][lane + k * 32] = v[k] * inv;
    }
    __syncthreads();

    // ---- Phase 2: out = attn @ values (coalesced values loads) ----
    const float* vbase = values + (size_t)b * TK_ * DV_ + tid;
    float oacc[IT_];
    #pragma unroll
    for (int i = 0; i < IT_; i++) oacc[i] = 0.f;

    #pragma unroll 2
    for (int j4 = 0; j4 < TK_ / 4; j4++) {
        float v0 = vbase[(j4 * 4 + 0) * DV_];
        float v1 = vbase[(j4 * 4 + 1) * DV_];
        float v2 = vbase[(j4 * 4 + 2) * DV_];
        float v3 = vbase[(j4 * 4 + 3) * DV_];
        #pragma unroll
        for (int i = 0; i < IT_; i++) {
            float4 a = ((const float4*)s_sc[i])[j4];
            oacc[i] += a.x * v0;
            oacc[i] += a.y * v1;
            oacc[i] += a.z * v2;
            oacc[i] += a.w * v3;
        }
    }
    #pragma unroll
    for (int i = 0; i < IT_; i++)
        out[((size_t)b * TQ_ + i0 + i) * DV_ + tid] = oacc[i];
}

extern "C" void kernel_launch(void* const* d_in, const int* in_sizes, int n_in,
                              void* d_out, int out_size)
{
    const float* queries    = (const float*)d_in[0];
    const float* keys       = (const float*)d_in[1];
    const float* values     = (const float*)d_in[2];
    const int*   valid_lens = (const int*)d_in[3];
    const float* wq         = (const float*)d_in[4];
    const float* wk         = (const float*)d_in[5];
    const float* wv         = (const float*)d_in[6];
    float*       out        = (float*)d_out;

    const int proj_blocks = (B_ * TQ_ + B_ * TK_) / 32;       // 192
    proj_kernel<<<proj_blocks, 256>>>(queries, keys, wq, wk);
    attn_kernel<<<(B_ * TQ_) / IT_, 256>>>(values, valid_lens, wv, out);
}

// round 5
// speedup vs baseline: 1.0577x; 1.0577x over previous
#include <cuda_runtime.h>
#include <cuda_bf16.h>
#include <cstdint>

#define B_   16
#define TQ_  128
#define TK_  256
#define DIN_ 64
#define H_   256
#define DV_  256
#define IT_  4
#define NEGV (-1000000.0f)

// Scratch (static device arrays: allocation-free).
__device__ float g_q [B_ * TQ_ * H_];   // [B, Tq, H]
__device__ float g_kT[B_ * H_ * TK_];   // [B, H, Tk]  (TRANSPOSED keys proj)

__device__ __forceinline__ float fast_tanh(float x) {
    float y;
    asm("tanh.approx.f32 %0, %1;" : "=f"(y) : "f"(x));
    return y;
}

// ---------------------------------------------------------------------------
// Kernel 1a: g_q = queries @ wq   (layout [B,Tq,H], coalesced everywhere)
// ---------------------------------------------------------------------------
__global__ __launch_bounds__(256) void proj_q_kernel(
    const float* __restrict__ queries, const float* __restrict__ wq)
{
    constexpr int RPB = 32;
    const int row0 = blockIdx.x * RPB;
    const int tid = threadIdx.x;

    float w[DIN_];
    #pragma unroll
    for (int d = 0; d < DIN_; d++) w[d] = wq[d * H_ + tid];   // coalesced

    __shared__ __align__(16) float s_x[RPB][DIN_];            // 8 KB
    const float* xb = queries + (size_t)row0 * DIN_;
    #pragma unroll
    for (int k = 0; k < (RPB * DIN_) / 256; k++)
        ((float*)s_x)[tid + k * 256] = xb[tid + k * 256];
    __syncthreads();

    #pragma unroll 4
    for (int r = 0; r < RPB; r++) {
        const float4* xr = (const float4*)s_x[r];
        float acc = 0.f;
        #pragma unroll
        for (int d4 = 0; d4 < DIN_ / 4; d4++) {
            float4 xv = xr[d4];
            acc += xv.x * w[d4 * 4 + 0];
            acc += xv.y * w[d4 * 4 + 1];
            acc += xv.z * w[d4 * 4 + 2];
            acc += xv.w * w[d4 * 4 + 3];
        }
        g_q[(size_t)(row0 + r) * H_ + tid] = acc;
    }
}

// ---------------------------------------------------------------------------
// Kernel 1b: g_kT[b][h][t] = (keys @ wk)^T.
// Block = (batch b, 32-wide h-chunk). Thread t owns key row t: holds the
// keys row in 64 registers, loops 32 h-columns (wk col broadcast from SMEM),
// writes g_kT coalesced (lanes = consecutive t).
// ---------------------------------------------------------------------------
__global__ __launch_bounds__(256) void proj_kT_kernel(
    const float* __restrict__ keys, const float* __restrict__ wk)
{
    const int b  = blockIdx.x >> 3;
    const int h0 = (blockIdx.x & 7) * 32;
    const int t  = threadIdx.x;            // key row 0..255

    float x[DIN_];
    const float4* kr = (const float4*)(keys + ((size_t)b * TK_ + t) * DIN_);
    #pragma unroll
    for (int d4 = 0; d4 < DIN_ / 4; d4++) {
        float4 v = kr[d4];
        x[d4 * 4 + 0] = v.x; x[d4 * 4 + 1] = v.y;
        x[d4 * 4 + 2] = v.z; x[d4 * 4 + 3] = v.w;
    }

    __shared__ float s_w[32][DIN_ + 1];    // wk columns h0..h0+31, padded
    #pragma unroll
    for (int k = 0; k < (32 * DIN_) / 256; k++) {
        int idx = t + k * 256;             // idx -> (d, hh)
        int hh = idx & 31, d = idx >> 5;
        s_w[hh][d] = wk[d * H_ + h0 + hh]; // coalesced over hh
    }
    __syncthreads();

    float* outb = g_kT + ((size_t)b * H_ + h0) * TK_ + t;
    #pragma unroll 2
    for (int hh = 0; hh < 32; hh++) {
        float acc = 0.f;
        #pragma unroll
        for (int d = 0; d < DIN_; d++) acc += x[d] * s_w[hh][d];
        outb[(size_t)hh * TK_] = acc;      // coalesced (lanes = t)
    }
}

// ---------------------------------------------------------------------------
// Kernel 2: fused scores + masked softmax + attn@V.
// CTA = (batch b, 4-query tile); 512 CTAs x 256 threads.
//   Phase 1: kt=tid&63 owns keys 4kt..4kt+3, qg=tid>>6 owns query i0+qg.
//            k loads are COALESCED float4 along Tk from g_kT; q/wv are
//            per-warp-uniform broadcast LDS.128. Depth-4 k prefetch.
//   Softmax: warps 0..3 each own one row, in-SMEM.
//   Phase 2: thread t owns output column v=t; coalesced values loads.
// ---------------------------------------------------------------------------
__global__ __launch_bounds__(256, 4) void attn_kernel(
    const float* __restrict__ values, const int* __restrict__ valid_lens,
    const float* __restrict__ wv, float* __restrict__ out)
{
    const int b  = blockIdx.x >> 5;          // 32 q-tiles per batch
    const int i0 = (blockIdx.x & 31) * IT_;
    const int tid = threadIdx.x;
    const int kt = tid & 63;                 // key group (4 keys)
    const int qg = tid >> 6;                 // query index within tile

    __shared__ __align__(16) float s_q[IT_][H_];    // 4 KB
    __shared__ __align__(16) float s_wv[H_];        // 1 KB
    __shared__ __align__(16) float s_sc[IT_][TK_];  // 4 KB

    s_wv[tid] = wv[tid];
    #pragma unroll
    for (int i = 0; i < IT_; i++)
        s_q[i][tid] = g_q[((size_t)b * TQ_ + i0 + i) * H_ + tid];
    const int vl = valid_lens[b];
    __syncthreads();

    // ---- Phase 1: scores (MUFU.TANH-bound, coalesced k stream) ----
    const float4* kbase = (const float4*)(g_kT + (size_t)b * H_ * TK_) + kt;
    // kbase[h * 64] = keys {4kt..4kt+3} at hidden-dim h.

    float acc0 = 0.f, acc1 = 0.f, acc2 = 0.f, acc3 = 0.f;
    float4 kbuf[4];
    #pragma unroll
    for (int p = 0; p < 4; p++) kbuf[p] = kbase[p * (TK_ / 4)];

    #pragma unroll 4
    for (int g = 0; g < H_ / 4; g++) {
        float4 cur[4];
        #pragma unroll
        for (int p = 0; p < 4; p++) cur[p] = kbuf[p];
        #pragma unroll
        for (int p = 0; p < 4; p++) {
            int hn = ((g + 1) * 4 + p) & (H_ - 1);   // wrap: safe, cheap
            kbuf[p] = kbase[hn * (TK_ / 4)];
        }
        float4 qv  = ((const float4*)s_q[qg])[g];    // broadcast LDS.128
        float4 wvv = ((const float4*)s_wv)[g];       // broadcast LDS.128
        #pragma unroll
        for (int p = 0; p < 4; p++) {
            float qh  = (p == 0) ? qv.x  : (p == 1) ? qv.y  : (p == 2) ? qv.z  : qv.w;
            float wvh = (p == 0) ? wvv.x : (p == 1) ? wvv.y : (p == 2) ? wvv.z : wvv.w;
            acc0 += wvh * fast_tanh(qh + cur[p].x);
            acc1 += wvh * fast_tanh(qh + cur[p].y);
            acc2 += wvh * fast_tanh(qh + cur[p].z);
            acc3 += wvh * fast_tanh(qh + cur[p].w);
        }
    }

    {
        float4 sc;
        sc.x = (4 * kt + 0 < vl) ? acc0 : NEGV;
        sc.y = (4 * kt + 1 < vl) ? acc1 : NEGV;
        sc.z = (4 * kt + 2 < vl) ? acc2 : NEGV;
        sc.w = (4 * kt + 3 < vl) ? acc3 : NEGV;
        ((float4*)s_sc[qg])[kt] = sc;                // STS.128, conflict-free
    }
    __syncthreads();

    // ---- Masked softmax: warp w (< IT_) handles row i=w ----
    if (tid < IT_ * 32) {
        const int i = tid >> 5, lane = tid & 31;
        float v[TK_ / 32];
        float m = -3.402823466e38f;
        #pragma unroll
        for (int k = 0; k < TK_ / 32; k++) {
            v[k] = s_sc[i][lane + k * 32];
            m = fmaxf(m, v[k]);
        }
        #pragma unroll
        for (int off = 16; off; off >>= 1)
            m = fmaxf(m, __shfl_xor_sync(0xffffffffu, m, off));
        float sum = 0.f;
        #pragma unroll
        for (int k = 0; k < TK_ / 32; k++) {
            v[k] = __expf(v[k] - m);
            sum += v[k];
        }
        #pragma unroll
        for (int off = 16; off; off >>= 1)
            sum += __shfl_xor_sync(0xffffffffu, sum, off);
        const float inv = 1.0f / sum;
        #pragma unroll
        for (int k = 0; k < TK_ / 32; k++)
            s_sc[i][lane + k * 32] = v[k] * inv;
    }
    __syncthreads();

    // ---- Phase 2: out = attn @ values (coalesced values loads) ----
    const float* vbase = values + (size_t)b * TK_ * DV_ + tid;
    float oacc[IT_];
    #pragma unroll
    for (int i = 0; i < IT_; i++) oacc[i] = 0.f;

    #pragma unroll 2
    for (int j4 = 0; j4 < TK_ / 4; j4++) {
        float v0 = vbase[(j4 * 4 + 0) * DV_];
        float v1 = vbase[(j4 * 4 + 1) * DV_];
        float v2 = vbase[(j4 * 4 + 2) * DV_];
        float v3 = vbase[(j4 * 4 + 3) * DV_];
        #pragma unroll
        for (int i = 0; i < IT_; i++) {
            float4 a = ((const float4*)s_sc[i])[j4];
            oacc[i] += a.x * v0;
            oacc[i] += a.y * v1;
            oacc[i] += a.z * v2;
            oacc[i] += a.w * v3;
        }
    }
    #pragma unroll
    for (int i = 0; i < IT_; i++)
        out[((size_t)b * TQ_ + i0 + i) * DV_ + tid] = oacc[i];
}

extern "C" void kernel_launch(void* const* d_in, const int* in_sizes, int n_in,
                              void* d_out, int out_size)
{
    const float* queries    = (const float*)d_in[0];
    const float* keys       = (const float*)d_in[1];
    const float* values     = (const float*)d_in[2];
    const int*   valid_lens = (const int*)d_in[3];
    const float* wq         = (const float*)d_in[4];
    const float* wk         = (const float*)d_in[5];
    const float* wv         = (const float*)d_in[6];
    float*       out        = (float*)d_out;

    proj_q_kernel <<<(B_ * TQ_) / 32, 256>>>(queries, wq);
    proj_kT_kernel<<<B_ * (H_ / 32), 256>>>(keys, wk);
    attn_kernel   <<<(B_ * TQ_) / IT_, 256>>>(values, valid_lens, wv, out);
}

// round 6
// speedup vs baseline: 1.2878x; 1.2175x over previous
#include <cuda_runtime.h>
#include <cuda_bf16.h>
#include <cstdint>

#define B_   16
#define TQ_  128
#define TK_  256
#define DIN_ 64
#define H_   256
#define DV_  256
#define IT_  4
#define NEGV (-1000000.0f)

// Scratch (static device arrays: allocation-free). g_kT padded by 4 h-rows so
// the attn prefetch can run past h=255 without wrap arithmetic.
__device__ float g_q [B_ * TQ_ * H_];            // [B*Tq, H]
__device__ float g_kT[B_ * H_ * TK_ + 4 * TK_];  // [B, H, Tk] + pad

__device__ __forceinline__ float fast_tanh(float x) {
    float y;
    asm("tanh.approx.f32 %0, %1;" : "=f"(y) : "f"(x));
    return y;
}

// ---------------------------------------------------------------------------
// Kernel 1 (fused projections), 384 blocks x 256 threads:
//   blocks [0,128):   g_q rows, 16 rows/block, thread owns column h=tid,
//                     wq column in regs, input rows broadcast from SMEM.
//   blocks [128,384): g_kT, block=(b, 16-h chunk), thread t owns key row t
//                     (row in regs), wk columns broadcast from SMEM,
//                     coalesced transposed stores.
// ---------------------------------------------------------------------------
__global__ __launch_bounds__(256) void proj_kernel(
    const float* __restrict__ queries, const float* __restrict__ keys,
    const float* __restrict__ wq, const float* __restrict__ wk)
{
    __shared__ __align__(16) float s_buf[16 * 65];   // shared by both parts
    const int tid = threadIdx.x;
    const int blk = blockIdx.x;

    if (blk < 128) {
        // ---- q projection: rows [row0, row0+16) ----
        const int row0 = blk * 16;
        float w[DIN_];
        #pragma unroll
        for (int d = 0; d < DIN_; d++) w[d] = wq[d * H_ + tid];   // coalesced

        float* s_x = s_buf;                          // [16][64]
        const float* xb = queries + (size_t)row0 * DIN_;
        #pragma unroll
        for (int k = 0; k < 4; k++)
            s_x[tid + k * 256] = xb[tid + k * 256];
        __syncthreads();

        #pragma unroll 4
        for (int r = 0; r < 16; r++) {
            const float4* xr = (const float4*)(s_x + r * DIN_);
            float acc = 0.f;
            #pragma unroll
            for (int d4 = 0; d4 < DIN_ / 4; d4++) {
                float4 xv = xr[d4];
                acc += xv.x * w[d4 * 4 + 0];
                acc += xv.y * w[d4 * 4 + 1];
                acc += xv.z * w[d4 * 4 + 2];
                acc += xv.w * w[d4 * 4 + 3];
            }
            g_q[(size_t)(row0 + r) * H_ + tid] = acc;
        }
    } else {
        // ---- kT projection: batch b, h chunk [h0, h0+16) ----
        const int blk2 = blk - 128;
        const int b  = blk2 >> 4;
        const int h0 = (blk2 & 15) << 4;
        const int t  = tid;                          // key row 0..255

        float x[DIN_];
        const float4* kr = (const float4*)(keys + ((size_t)b * TK_ + t) * DIN_);
        #pragma unroll
        for (int d4 = 0; d4 < DIN_ / 4; d4++) {
            float4 v = kr[d4];
            x[d4 * 4 + 0] = v.x; x[d4 * 4 + 1] = v.y;
            x[d4 * 4 + 2] = v.z; x[d4 * 4 + 3] = v.w;
        }

        float (*s_w)[DIN_ + 1] = (float (*)[DIN_ + 1])s_buf;   // [16][65]
        #pragma unroll
        for (int k = 0; k < 4; k++) {
            int idx = tid + k * 256;                 // -> (hh, d)
            int hh = idx & 15, d = idx >> 4;
            s_w[hh][d] = wk[d * H_ + h0 + hh];
        }
        __syncthreads();

        float* outb = g_kT + ((size_t)b * H_ + h0) * TK_ + t;
        #pragma unroll 2
        for (int hh = 0; hh < 16; hh++) {
            float acc = 0.f;
            #pragma unroll
            for (int d = 0; d < DIN_; d++) acc += x[d] * s_w[hh][d];
            outb[(size_t)hh * TK_] = acc;            // coalesced over t
        }
    }
}

// ---------------------------------------------------------------------------
// Kernel 2: fused scores + masked softmax + attn@V.
// CTA = (batch b, 4-query tile); 512 CTAs x 512 threads (16 warps).
//   Phase 1: warp w -> (query qg = w>>2, key-quarter kq = w&3). Lane owns 2
//            consecutive keys (coalesced float2 along Tk from g_kT).
//            Warps whose key quarter is fully masked (kq*64 >= vl) SKIP the
//            tanh loop entirely and write NEG.
//   Softmax: warps 0..3 each own one row, in-SMEM.
//   Phase 2: threads <256 own output column v=tid; loop only to ceil(vl/4)
//            (masked attn weights are exactly 0).
// ---------------------------------------------------------------------------
__global__ __launch_bounds__(512, 2) void attn_kernel(
    const float* __restrict__ values, const int* __restrict__ valid_lens,
    const float* __restrict__ wv, float* __restrict__ out)
{
    const int b  = blockIdx.x >> 5;          // 32 q-tiles per batch
    const int i0 = (blockIdx.x & 31) * IT_;
    const int tid  = threadIdx.x;
    const int wid  = tid >> 5;
    const int lane = tid & 31;
    const int qg = wid >> 2;                 // query within tile
    const int kq = wid & 3;                  // 64-key quarter

    __shared__ __align__(16) float s_q[IT_][H_];    // 4 KB
    __shared__ __align__(16) float s_wv[H_];        // 1 KB
    __shared__ __align__(16) float s_sc[IT_][TK_];  // 4 KB

    if (tid < 256) s_wv[tid] = wv[tid];
    #pragma unroll
    for (int k = 0; k < 2; k++) {
        int idx = tid + k * 512;                    // -> (row, h)
        s_q[idx >> 8][idx & 255] =
            g_q[((size_t)b * TQ_ + i0 + (idx >> 8)) * H_ + (idx & 255)];
    }
    const int vl = valid_lens[b];
    __syncthreads();

    // ---- Phase 1: scores (warp-granularity mask skip) ----
    const int j0 = kq * 64 + 2 * lane;              // lane's first key
    if (kq * 64 < vl) {
        const float2* kp = (const float2*)(g_kT + (size_t)b * H_ * TK_)
                           + (kq * 32 + lane);      // h stride = TK_/2 float2
        float acc0 = 0.f, acc1 = 0.f;
        float2 kbuf[4];
        #pragma unroll
        for (int p = 0; p < 4; p++) kbuf[p] = kp[p * (TK_ / 2)];
        kp += 4 * (TK_ / 2);

        #pragma unroll 4
        for (int g = 0; g < H_ / 4; g++) {
            float2 cur[4];
            #pragma unroll
            for (int p = 0; p < 4; p++) cur[p] = kbuf[p];
            #pragma unroll
            for (int p = 0; p < 4; p++) kbuf[p] = kp[p * (TK_ / 2)];  // pad-safe
            kp += 4 * (TK_ / 2);

            float4 qv  = ((const float4*)s_q[qg])[g];   // broadcast LDS.128
            float4 wvv = ((const float4*)s_wv)[g];      // broadcast LDS.128
            #pragma unroll
            for (int p = 0; p < 4; p++) {
                float qh  = (p == 0) ? qv.x  : (p == 1) ? qv.y  : (p == 2) ? qv.z  : qv.w;
                float wvh = (p == 0) ? wvv.x : (p == 1) ? wvv.y : (p == 2) ? wvv.z : wvv.w;
                acc0 += wvh * fast_tanh(qh + cur[p].x);
                acc1 += wvh * fast_tanh(qh + cur[p].y);
            }
        }
        float2 sc;
        sc.x = (j0 + 0 < vl) ? acc0 : NEGV;
        sc.y = (j0 + 1 < vl) ? acc1 : NEGV;
        ((float2*)s_sc[qg])[kq * 32 + lane] = sc;
    } else {
        ((float2*)s_sc[qg])[kq * 32 + lane] = make_float2(NEGV, NEGV);
    }
    __syncthreads();

    // ---- Masked softmax: warps 0..3, one row each ----
    if (tid < IT_ * 32) {
        const int i = wid, l = lane;
        float v[TK_ / 32];
        float m = -3.402823466e38f;
        #pragma unroll
        for (int k = 0; k < TK_ / 32; k++) {
            v[k] = s_sc[i][l + k * 32];
            m = fmaxf(m, v[k]);
        }
        #pragma unroll
        for (int off = 16; off; off >>= 1)
            m = fmaxf(m, __shfl_xor_sync(0xffffffffu, m, off));
        float sum = 0.f;
        #pragma unroll
        for (int k = 0; k < TK_ / 32; k++) {
            v[k] = __expf(v[k] - m);
            sum += v[k];
        }
        #pragma unroll
        for (int off = 16; off; off >>= 1)
            sum += __shfl_xor_sync(0xffffffffu, sum, off);
        const float inv = 1.0f / sum;
        #pragma unroll
        for (int k = 0; k < TK_ / 32; k++)
            s_sc[i][l + k * 32] = v[k] * inv;
    }
    __syncthreads();

    // ---- Phase 2: out = attn @ values, only rows < vl (attn==0 beyond) ----
    if (tid < 256) {
        const int vl_p2 = (vl == 0) ? TK_ : vl;     // vl==0 -> uniform attn
        const int jmax4 = (vl_p2 + 3) >> 2;

        const float* vbase = values + (size_t)b * TK_ * DV_ + tid;
        float oacc[IT_];
        #pragma unroll
        for (int i = 0; i < IT_; i++) oacc[i] = 0.f;

        #pragma unroll 2
        for (int j4 = 0; j4 < jmax4; j4++) {
            float v0 = vbase[(j4 * 4 + 0) * DV_];
            float v1 = vbase[(j4 * 4 + 1) * DV_];
            float v2 = vbase[(j4 * 4 + 2) * DV_];
            float v3 = vbase[(j4 * 4 + 3) * DV_];
            #pragma unroll
            for (int i = 0; i < IT_; i++) {
                float4 a = ((const float4*)s_sc[i])[j4];
                oacc[i] += a.x * v0;
                oacc[i] += a.y * v1;
                oacc[i] += a.z * v2;
                oacc[i] += a.w * v3;
            }
        }
        #pragma unroll
        for (int i = 0; i < IT_; i++)
            out[((size_t)b * TQ_ + i0 + i) * DV_ + tid] = oacc[i];
    }
}

extern "C" void kernel_launch(void* const* d_in, const int* in_sizes, int n_in,
                              void* d_out, int out_size)
{
    const float* queries    = (const float*)d_in[0];
    const float* keys       = (const float*)d_in[1];
    const float* values     = (const float*)d_in[2];
    const int*   valid_lens = (const int*)d_in[3];
    const float* wq         = (const float*)d_in[4];
    const float* wk         = (const float*)d_in[5];
    const float* wv         = (const float*)d_in[6];
    float*       out        = (float*)d_out;

    proj_kernel<<<384, 256>>>(queries, keys, wq, wk);
    attn_kernel<<<(B_ * TQ_) / IT_, 512>>>(values, valid_lens, wv, out);
}